// round 1
// baseline (speedup 1.0000x reference)
#include <cuda_runtime.h>

// Problem constants
#define BB 4
#define SS 2048
#define DD 1024

// Scratch (allocation-free rule: __device__ globals)
__device__ float g_q[BB * SS * DD];        // 32 MB
__device__ float g_k[BB * SS * DD];        // 32 MB
__device__ float g_v[BB * SS * DD];        // 32 MB
__device__ float g_p[(size_t)BB * SS * SS]; // 64 MB, scores -> probs in place

// GEMM tiling
#define BM 64
#define BN 64
#define BK 16
#define TM 4
#define TN 4
// 256 threads = (BM/TM) x (BN/TN) = 16x16

// ---------------------------------------------------------------------------
// NN GEMM body: C[M,N] += A[M,K] * B[K,N], all row-major. kmax limits K loop
// (rounded to BK by callers). All dims divisible by tile sizes here.
// ---------------------------------------------------------------------------
__device__ __forceinline__ void gemm_nn_body(
    const float* __restrict__ A, const float* __restrict__ B,
    float* __restrict__ C, int M, int N, int K, int kmax)
{
    __shared__ float As[BK][BM + 4];
    __shared__ float Bs[BK][BN + 4];

    const int tid = threadIdx.x;
    const int tx = tid & 15;      // 0..15 -> N micro
    const int ty = tid >> 4;      // 0..15 -> M micro
    const int bm = blockIdx.y * BM;
    const int bn = blockIdx.x * BN;

    // A-tile load mapping: each thread loads float4 along K
    const int am = tid >> 2;          // 0..63 row within tile
    const int ak = (tid & 3) * 4;     // 0,4,8,12
    // B-tile load mapping: each thread loads float4 along N
    const int bk = tid >> 4;          // 0..15 row within tile
    const int bn4 = (tid & 15) * 4;   // 0..60

    float acc[TM][TN] = {};

    for (int k0 = 0; k0 < kmax; k0 += BK) {
        float4 a4 = *reinterpret_cast<const float4*>(
            A + (size_t)(bm + am) * K + k0 + ak);
        As[ak + 0][am] = a4.x;
        As[ak + 1][am] = a4.y;
        As[ak + 2][am] = a4.z;
        As[ak + 3][am] = a4.w;

        float4 b4 = *reinterpret_cast<const float4*>(
            B + (size_t)(k0 + bk) * N + bn + bn4);
        *reinterpret_cast<float4*>(&Bs[bk][bn4]) = b4;

        __syncthreads();

        #pragma unroll
        for (int kk = 0; kk < BK; kk++) {
            float4 av = *reinterpret_cast<const float4*>(&As[kk][ty * TM]);
            float4 bv = *reinterpret_cast<const float4*>(&Bs[kk][tx * TN]);
            float a[4] = {av.x, av.y, av.z, av.w};
            float b[4] = {bv.x, bv.y, bv.z, bv.w};
            #pragma unroll
            for (int i = 0; i < TM; i++)
                #pragma unroll
                for (int j = 0; j < TN; j++)
                    acc[i][j] += a[i] * b[j];
        }
        __syncthreads();
    }

    #pragma unroll
    for (int i = 0; i < TM; i++) {
        float4 o = make_float4(acc[i][0], acc[i][1], acc[i][2], acc[i][3]);
        *reinterpret_cast<float4*>(
            C + (size_t)(bm + ty * TM + i) * N + bn + tx * TN) = o;
    }
}

// ---------------------------------------------------------------------------
// NT GEMM body: C[M,N] = A[M,K] * Bt[N,K]^T  (both A and Bt are K-contiguous)
// ---------------------------------------------------------------------------
__device__ __forceinline__ void gemm_nt_body(
    const float* __restrict__ A, const float* __restrict__ Bt,
    float* __restrict__ C, int M, int N, int K)
{
    __shared__ float As[BK][BM + 4];
    __shared__ float Bs[BK][BN + 4];

    const int tid = threadIdx.x;
    const int tx = tid & 15;
    const int ty = tid >> 4;
    const int bm = blockIdx.y * BM;
    const int bn = blockIdx.x * BN;

    const int am = tid >> 2;
    const int ak = (tid & 3) * 4;

    float acc[TM][TN] = {};

    for (int k0 = 0; k0 < K; k0 += BK) {
        float4 a4 = *reinterpret_cast<const float4*>(
            A + (size_t)(bm + am) * K + k0 + ak);
        As[ak + 0][am] = a4.x;
        As[ak + 1][am] = a4.y;
        As[ak + 2][am] = a4.z;
        As[ak + 3][am] = a4.w;

        // Bt tile loaded exactly like A (row = n-index, contiguous along K)
        float4 b4 = *reinterpret_cast<const float4*>(
            Bt + (size_t)(bn + am) * K + k0 + ak);
        Bs[ak + 0][am] = b4.x;
        Bs[ak + 1][am] = b4.y;
        Bs[ak + 2][am] = b4.z;
        Bs[ak + 3][am] = b4.w;

        __syncthreads();

        #pragma unroll
        for (int kk = 0; kk < BK; kk++) {
            float4 av = *reinterpret_cast<const float4*>(&As[kk][ty * TM]);
            float4 bv = *reinterpret_cast<const float4*>(&Bs[kk][tx * TN]);
            float a[4] = {av.x, av.y, av.z, av.w};
            float b[4] = {bv.x, bv.y, bv.z, bv.w};
            #pragma unroll
            for (int i = 0; i < TM; i++)
                #pragma unroll
                for (int j = 0; j < TN; j++)
                    acc[i][j] += a[i] * b[j];
        }
        __syncthreads();
    }

    #pragma unroll
    for (int i = 0; i < TM; i++) {
        float4 o = make_float4(acc[i][0], acc[i][1], acc[i][2], acc[i][3]);
        *reinterpret_cast<float4*>(
            C + (size_t)(bm + ty * TM + i) * N + bn + tx * TN) = o;
    }
}

// ---------------------------------------------------------------------------
// Kernel 1: fused QKV projection. grid = (DD/BN, B*S/BM, 3)
// ---------------------------------------------------------------------------
__global__ __launch_bounds__(256) void qkv_gemm(
    const float* __restrict__ X,
    const float* __restrict__ Wq,
    const float* __restrict__ Wk,
    const float* __restrict__ Wv)
{
    const float* W = (blockIdx.z == 0) ? Wq : (blockIdx.z == 1) ? Wk : Wv;
    float* O = (blockIdx.z == 0) ? g_q : (blockIdx.z == 1) ? g_k : g_v;
    gemm_nn_body(X, W, O, BB * SS, DD, DD, DD);
}

// ---------------------------------------------------------------------------
// Kernel 2: scores = Q K^T per batch, causal block-skip. grid = (S/BN, S/BM, B)
// ---------------------------------------------------------------------------
__global__ __launch_bounds__(256) void scores_gemm()
{
    // Fully-masked tile: every column index > every row index -> skip.
    if ((int)blockIdx.x * BN > (int)blockIdx.y * BM + (BM - 1)) return;
    const size_t b = blockIdx.z;
    gemm_nt_body(g_q + b * SS * DD, g_k + b * SS * DD,
                 g_p + b * SS * SS, SS, SS, DD);
}

// ---------------------------------------------------------------------------
// Kernel 3: in-place causal softmax of scores/sqrt(dk). One block per row.
// ---------------------------------------------------------------------------
__global__ __launch_bounds__(256) void softmax_causal()
{
    const int row = blockIdx.x;            // 0 .. B*S-1
    const int q = row & (SS - 1);
    float* srow = g_p + (size_t)row * SS;
    const int n = q + 1;                   // valid length
    const float inv = 0.03125f;            // 1/sqrt(1024)

    __shared__ float red[256];
    const int t = threadIdx.x;

    // max over valid region (scale commutes with max since inv > 0)
    float m = -3.402823466e38f;
    for (int i = t; i < n; i += 256) m = fmaxf(m, srow[i]);
    red[t] = m;
    __syncthreads();
    for (int s = 128; s > 0; s >>= 1) {
        if (t < s) red[t] = fmaxf(red[t], red[t + s]);
        __syncthreads();
    }
    m = red[0] * inv;
    __syncthreads();

    // exp and sum
    float sum = 0.f;
    for (int i = t; i < n; i += 256) {
        float e = expf(srow[i] * inv - m);
        srow[i] = e;
        sum += e;
    }
    red[t] = sum;
    __syncthreads();
    for (int s = 128; s > 0; s >>= 1) {
        if (t < s) red[t] += red[t + s];
        __syncthreads();
    }
    const float r = 1.f / red[0];
    __syncthreads();

    // normalize valid region; zero masked region (PV reads full rows)
    for (int i = t; i < n; i += 256) srow[i] *= r;
    for (int i = n + t; i < SS; i += 256) srow[i] = 0.f;
}

// ---------------------------------------------------------------------------
// Kernel 4: out = P V per batch, causal K-limit. grid = (DD/BN, S/BM, B)
// ---------------------------------------------------------------------------
__global__ __launch_bounds__(256) void pv_gemm(float* __restrict__ out)
{
    const size_t b = blockIdx.z;
    // Rows [bm, bm+BM) only attend to keys k <= bm+BM-1 -> limit K loop.
    int kmax = (int)blockIdx.y * BM + BM;
    if (kmax > SS) kmax = SS;
    gemm_nn_body(g_p + b * SS * SS, g_v + b * SS * DD,
                 out + b * SS * DD, SS, DD, SS, kmax);
}

// ---------------------------------------------------------------------------
extern "C" void kernel_launch(void* const* d_in, const int* in_sizes, int n_in,
                              void* d_out, int out_size)
{
    (void)in_sizes; (void)n_in; (void)out_size;
    const float* x  = (const float*)d_in[0];
    const float* Wq = (const float*)d_in[1];
    const float* Wk = (const float*)d_in[2];
    const float* Wv = (const float*)d_in[3];
    float* out = (float*)d_out;

    dim3 blk(256);
    qkv_gemm<<<dim3(DD / BN, (BB * SS) / BM, 3), blk>>>(x, Wq, Wk, Wv);
    scores_gemm<<<dim3(SS / BN, SS / BM, BB), blk>>>();
    softmax_causal<<<dim3(BB * SS), blk>>>();
    pv_gemm<<<dim3(DD / BN, SS / BM, BB), blk>>>(out);
}

// round 3
// speedup vs baseline: 2.3904x; 2.3904x over previous
#include <cuda_runtime.h>
#include <cstdint>

// Problem constants
#define BB 4
#define SS 2048
#define DD 1024

// Scratch (allocation-free rule: __device__ globals)
__device__ float g_q[BB * SS * DD];          // 32 MB
__device__ float g_k[BB * SS * DD];          // 32 MB
__device__ float g_v[BB * SS * DD];          // 32 MB
__device__ float g_vt[BB * SS * DD];         // 32 MB (V^T per batch: [D, S])
__device__ float g_wt[3 * DD * DD];          // 12 MB (W^T: [D_out, D_in])
__device__ float g_p[(size_t)BB * SS * SS];  // 64 MB, scores -> probs in place

// ---------------------------------------------------------------------------
// tf32 mma.sync GEMM: C[M,N] = A[M,K] * B[N,K]^T, A and B K-contiguous.
// Block tile 128x128, k-tile 32, 256 threads, warp tile 64x32.
// Smem row stride 36 floats: frag-load bank index = (4*r + c) % 32 = lane id
// -> conflict-free; rows stay 16B aligned (144 B).
// ---------------------------------------------------------------------------
#define TILE 128
#define KT 32
#define SSTR 36
#define BUF_FLOATS (2 * TILE * SSTR)            // A+B for one stage
#define SMEM_FLOATS (2 * BUF_FLOATS)            // two stages
#define SMEM_BYTES (SMEM_FLOATS * 4)            // 73728

__device__ __forceinline__ uint32_t smem_u32(const void* p) {
    uint32_t a;
    asm("{ .reg .u64 t; cvta.to.shared.u64 t, %1; cvt.u32.u64 %0, t; }"
        : "=r"(a) : "l"(p));
    return a;
}
__device__ __forceinline__ uint32_t tf32_of(float x) {
    uint32_t r; asm("cvt.rna.tf32.f32 %0, %1;" : "=r"(r) : "f"(x)); return r;
}
__device__ __forceinline__ void cp16(uint32_t dst, const float* src) {
    asm volatile("cp.async.cg.shared.global [%0], [%1], 16;"
                 :: "r"(dst), "l"(src) : "memory");
}
__device__ __forceinline__ void mma_tf32(float* c, const uint32_t* a, const uint32_t* b) {
    asm volatile(
        "mma.sync.aligned.m16n8k8.row.col.f32.tf32.tf32.f32 "
        "{%0,%1,%2,%3}, {%4,%5,%6,%7}, {%8,%9}, {%0,%1,%2,%3};"
        : "+f"(c[0]), "+f"(c[1]), "+f"(c[2]), "+f"(c[3])
        : "r"(a[0]), "r"(a[1]), "r"(a[2]), "r"(a[3]), "r"(b[0]), "r"(b[1]));
}

__device__ __forceinline__ void tc_gemm_body(
    const float* __restrict__ A, const float* __restrict__ B, float* __restrict__ C,
    int ldA, int ldB, int ldC, int kmax, float* smem)
{
    const int tid = threadIdx.x;
    const int wid = tid >> 5;
    const int lid = tid & 31;
    const int gid = lid >> 2;        // group id 0..7
    const int tq  = lid & 3;         // thread-in-group 0..3
    const int wm  = wid >> 2;        // 0..1 -> 64-row half
    const int wn  = wid & 3;         // 0..3 -> 32-col quarter
    const int bm = blockIdx.y * TILE;
    const int bn = blockIdx.x * TILE;

    const uint32_t sb = smem_u32(smem);

    // cp.async loader mapping: row = tid>>1, four 16B chunks per thread
    const int lrow = tid >> 1;
    const int lc0  = (tid & 1) * 4;               // chunk 0..3 or 4..7
    const float* ag = A + (size_t)(bm + lrow) * ldA + lc0 * 4;
    const float* bg = B + (size_t)(bn + lrow) * ldB + lc0 * 4;
    const uint32_t sa_off = (uint32_t)(lrow * SSTR + lc0 * 4) * 4u;

    const int nkt = kmax / KT;

    // Prologue: stage 0
    {
        uint32_t da = sb + sa_off;
        uint32_t db = sb + (uint32_t)TILE * SSTR * 4u + sa_off;
        #pragma unroll
        for (int j = 0; j < 4; j++) {
            cp16(da + 16u * j, ag + 4 * j);
            cp16(db + 16u * j, bg + 4 * j);
        }
        asm volatile("cp.async.commit_group;" ::: "memory");
    }

    float acc[4][4][4];
    #pragma unroll
    for (int mt = 0; mt < 4; mt++)
        #pragma unroll
        for (int nt = 0; nt < 4; nt++)
            #pragma unroll
            for (int r = 0; r < 4; r++) acc[mt][nt][r] = 0.f;

    for (int kt = 0; kt < nkt; kt++) {
        const int buf = kt & 1;
        // Issue next stage before waiting on current
        if (kt + 1 < nkt) {
            const int nb = (kt + 1) & 1;
            uint32_t da = sb + (uint32_t)nb * BUF_FLOATS * 4u + sa_off;
            uint32_t db = da + (uint32_t)TILE * SSTR * 4u;
            const float* ag2 = ag + (size_t)(kt + 1) * KT;
            const float* bg2 = bg + (size_t)(kt + 1) * KT;
            #pragma unroll
            for (int j = 0; j < 4; j++) {
                cp16(da + 16u * j, ag2 + 4 * j);
                cp16(db + 16u * j, bg2 + 4 * j);
            }
            asm volatile("cp.async.commit_group;" ::: "memory");
            asm volatile("cp.async.wait_group 1;" ::: "memory");
        } else {
            asm volatile("cp.async.wait_group 0;" ::: "memory");
        }
        __syncthreads();

        const float* As = smem + buf * BUF_FLOATS;
        const float* Bs = As + TILE * SSTR;

        #pragma unroll
        for (int ks = 0; ks < 4; ks++) {
            const int kk = ks * 8 + tq;
            uint32_t af[4][4], bf[4][2];
            #pragma unroll
            for (int mt = 0; mt < 4; mt++) {
                const float* ar = As + (wm * 64 + mt * 16 + gid) * SSTR + kk;
                af[mt][0] = tf32_of(ar[0]);
                af[mt][1] = tf32_of(ar[8 * SSTR]);
                af[mt][2] = tf32_of(ar[4]);
                af[mt][3] = tf32_of(ar[8 * SSTR + 4]);
            }
            #pragma unroll
            for (int nt = 0; nt < 4; nt++) {
                const float* br = Bs + (wn * 32 + nt * 8 + gid) * SSTR + kk;
                bf[nt][0] = tf32_of(br[0]);
                bf[nt][1] = tf32_of(br[4]);
            }
            #pragma unroll
            for (int mt = 0; mt < 4; mt++)
                #pragma unroll
                for (int nt = 0; nt < 4; nt++)
                    mma_tf32(acc[mt][nt], af[mt], bf[nt]);
        }
        __syncthreads();
    }

    // Epilogue: c0,c1 at (row, 2*tq), c2,c3 at (row+8, 2*tq)
    #pragma unroll
    for (int mt = 0; mt < 4; mt++) {
        const int r0 = bm + wm * 64 + mt * 16 + gid;
        #pragma unroll
        for (int nt = 0; nt < 4; nt++) {
            const int c0 = bn + wn * 32 + nt * 8 + tq * 2;
            *reinterpret_cast<float2*>(C + (size_t)r0 * ldC + c0) =
                make_float2(acc[mt][nt][0], acc[mt][nt][1]);
            *reinterpret_cast<float2*>(C + (size_t)(r0 + 8) * ldC + c0) =
                make_float2(acc[mt][nt][2], acc[mt][nt][3]);
        }
    }
}

// ---------------------------------------------------------------------------
// GEMM kernel wrappers
// ---------------------------------------------------------------------------
__global__ __launch_bounds__(256, 2) void qkv_tc(const float* __restrict__ X) {
    extern __shared__ float smem[];
    const float* Bz = g_wt + (size_t)blockIdx.z * DD * DD;
    float* Cz = (blockIdx.z == 0) ? g_q : (blockIdx.z == 1) ? g_k : g_v;
    tc_gemm_body(X, Bz, Cz, DD, DD, DD, DD, smem);
}

__global__ __launch_bounds__(256, 2) void scores_tc() {
    if (blockIdx.x > blockIdx.y) return;   // fully-masked tile
    extern __shared__ float smem[];
    size_t b = blockIdx.z;
    tc_gemm_body(g_q + b * SS * DD, g_k + b * SS * DD,
                 g_p + b * (size_t)SS * SS, DD, DD, SS, DD, smem);
}

__global__ __launch_bounds__(256, 2) void pv_tc(float* __restrict__ out) {
    extern __shared__ float smem[];
    size_t b = blockIdx.z;
    int kmax = (int)(blockIdx.y + 1) * TILE;
    if (kmax > SS) kmax = SS;
    tc_gemm_body(g_p + b * (size_t)SS * SS, g_vt + b * SS * DD,
                 out + b * SS * DD, SS, SS, DD, kmax, smem);
}

// ---------------------------------------------------------------------------
// Transposes: out[c*rows + r] = in[r*cols + c]
// ---------------------------------------------------------------------------
__device__ __forceinline__ void transpose_body(
    const float* __restrict__ in, float* __restrict__ out, int rows, int cols)
{
    __shared__ float t[32][33];
    const int tx = threadIdx.x, ty = threadIdx.y;
    const int bx = blockIdx.x * 32, by = blockIdx.y * 32;
    #pragma unroll
    for (int i = 0; i < 32; i += 8)
        t[ty + i][tx] = in[(size_t)(by + ty + i) * cols + bx + tx];
    __syncthreads();
    #pragma unroll
    for (int i = 0; i < 32; i += 8)
        out[(size_t)(bx + ty + i) * rows + by + tx] = t[tx][ty + i];
}

__global__ void transpose_w(const float* __restrict__ Wq,
                            const float* __restrict__ Wk,
                            const float* __restrict__ Wv) {
    const float* in = (blockIdx.z == 0) ? Wq : (blockIdx.z == 1) ? Wk : Wv;
    transpose_body(in, g_wt + (size_t)blockIdx.z * DD * DD, DD, DD);
}

__global__ void transpose_v() {
    size_t b = blockIdx.z;
    transpose_body(g_v + b * SS * DD, g_vt + b * SS * DD, SS, DD);
}

// ---------------------------------------------------------------------------
// Causal softmax (known-correct)
// ---------------------------------------------------------------------------
__global__ __launch_bounds__(256) void softmax_causal()
{
    const int row = blockIdx.x;
    const int q = row & (SS - 1);
    float* srow = g_p + (size_t)row * SS;
    const int n = q + 1;
    const float inv = 0.03125f;   // 1/sqrt(1024)

    __shared__ float red[256];
    const int t = threadIdx.x;

    float m = -3.402823466e38f;
    for (int i = t; i < n; i += 256) m = fmaxf(m, srow[i]);
    red[t] = m;
    __syncthreads();
    for (int s = 128; s > 0; s >>= 1) {
        if (t < s) red[t] = fmaxf(red[t], red[t + s]);
        __syncthreads();
    }
    m = red[0] * inv;
    __syncthreads();

    float sum = 0.f;
    for (int i = t; i < n; i += 256) {
        float e = expf(srow[i] * inv - m);
        srow[i] = e;
        sum += e;
    }
    red[t] = sum;
    __syncthreads();
    for (int s = 128; s > 0; s >>= 1) {
        if (t < s) red[t] += red[t + s];
        __syncthreads();
    }
    const float r = 1.f / red[0];
    __syncthreads();

    for (int i = t; i < n; i += 256) srow[i] *= r;
    for (int i = n + t; i < SS; i += 256) srow[i] = 0.f;
}

// ---------------------------------------------------------------------------
extern "C" void kernel_launch(void* const* d_in, const int* in_sizes, int n_in,
                              void* d_out, int out_size)
{
    (void)in_sizes; (void)n_in; (void)out_size;
    const float* x  = (const float*)d_in[0];
    const float* Wq = (const float*)d_in[1];
    const float* Wk = (const float*)d_in[2];
    const float* Wv = (const float*)d_in[3];
    float* out = (float*)d_out;

    cudaFuncSetAttribute(qkv_tc,    cudaFuncAttributeMaxDynamicSharedMemorySize, SMEM_BYTES);
    cudaFuncSetAttribute(scores_tc, cudaFuncAttributeMaxDynamicSharedMemorySize, SMEM_BYTES);
    cudaFuncSetAttribute(pv_tc,     cudaFuncAttributeMaxDynamicSharedMemorySize, SMEM_BYTES);

    dim3 t32(32, 8);
    transpose_w<<<dim3(DD / 32, DD / 32, 3), t32>>>(Wq, Wk, Wv);
    qkv_tc<<<dim3(DD / TILE, (BB * SS) / TILE, 3), 256, SMEM_BYTES>>>(x);
    transpose_v<<<dim3(DD / 32, SS / 32, BB), t32>>>();
    scores_tc<<<dim3(SS / TILE, SS / TILE, BB), 256, SMEM_BYTES>>>();
    softmax_causal<<<dim3(BB * SS), 256>>>();
    pv_tc<<<dim3(DD / TILE, SS / TILE, BB), 256, SMEM_BYTES>>>(out);
}

// round 4
// speedup vs baseline: 2.4607x; 1.0294x over previous
#include <cuda_runtime.h>
#include <cstdint>

// Problem constants
#define BB 4
#define SS 2048
#define DD 1024

// Scratch (allocation-free rule: __device__ globals). All tf32-pre-rounded
// except g_p scores (rounded only at softmax output).
__device__ float g_x[BB * SS * DD];          // 32 MB  X rounded
__device__ float g_q[BB * SS * DD];          // 32 MB
__device__ float g_k[BB * SS * DD];          // 32 MB
__device__ float g_v[BB * SS * DD];          // 32 MB
__device__ float g_vt[BB * SS * DD];         // 32 MB (V^T per batch: [D, S])
__device__ float g_wt[3 * DD * DD];          // 12 MB (W^T: [D_out, D_in])
__device__ float g_p[(size_t)BB * SS * SS];  // 64 MB, scores -> probs in place

// ---------------------------------------------------------------------------
// tf32 mma.sync GEMM: C[M,N] = A[M,K] * B[N,K]^T, A and B K-contiguous and
// already tf32-rounded. Block tile 128x128, k-tile 32, 256 threads,
// warp tile 64x32. Smem row stride 36 floats -> conflict-free frag loads.
// ---------------------------------------------------------------------------
#define TILE 128
#define KT 32
#define SSTR 36
#define BUF_FLOATS (2 * TILE * SSTR)            // A+B for one stage
#define SMEM_FLOATS (2 * BUF_FLOATS)            // two stages
#define SMEM_BYTES (SMEM_FLOATS * 4)            // 73728

__device__ __forceinline__ uint32_t smem_u32(const void* p) {
    uint32_t a;
    asm("{ .reg .u64 t; cvta.to.shared.u64 t, %1; cvt.u32.u64 %0, t; }"
        : "=r"(a) : "l"(p));
    return a;
}
__device__ __forceinline__ float tf32r(float x) {   // round-to-nearest tf32
    float r; asm("cvt.rna.tf32.f32 %0, %1;" : "=f"(r) : "f"(x)); return r;
}
__device__ __forceinline__ void cp16(uint32_t dst, const float* src) {
    asm volatile("cp.async.cg.shared.global [%0], [%1], 16;"
                 :: "r"(dst), "l"(src) : "memory");
}
__device__ __forceinline__ void mma_tf32(float* c, const uint32_t* a, const uint32_t* b) {
    asm volatile(
        "mma.sync.aligned.m16n8k8.row.col.f32.tf32.tf32.f32 "
        "{%0,%1,%2,%3}, {%4,%5,%6,%7}, {%8,%9}, {%0,%1,%2,%3};"
        : "+f"(c[0]), "+f"(c[1]), "+f"(c[2]), "+f"(c[3])
        : "r"(a[0]), "r"(a[1]), "r"(a[2]), "r"(a[3]), "r"(b[0]), "r"(b[1]));
}

template<bool ROUND_C>
__device__ __forceinline__ void tc_gemm_body(
    const float* __restrict__ A, const float* __restrict__ B, float* __restrict__ C,
    int ldA, int ldB, int ldC, int kmax, int bm, int bn, float* smem)
{
    const int tid = threadIdx.x;
    const int wid = tid >> 5;
    const int lid = tid & 31;
    const int gid = lid >> 2;        // group id 0..7
    const int tq  = lid & 3;         // thread-in-group 0..3
    const int wm  = wid >> 2;        // 0..1 -> 64-row half
    const int wn  = wid & 3;         // 0..3 -> 32-col quarter

    const uint32_t sb = smem_u32(smem);

    // cp.async loader mapping: row = tid>>1, four 16B chunks per thread
    const int lrow = tid >> 1;
    const int lc0  = (tid & 1) * 4;               // chunk 0..3 or 4..7
    const float* ag = A + (size_t)(bm + lrow) * ldA + lc0 * 4;
    const float* bg = B + (size_t)(bn + lrow) * ldB + lc0 * 4;
    const uint32_t sa_off = (uint32_t)(lrow * SSTR + lc0 * 4) * 4u;

    const int nkt = kmax / KT;

    // Prologue: stage 0
    {
        uint32_t da = sb + sa_off;
        uint32_t db = sb + (uint32_t)TILE * SSTR * 4u + sa_off;
        #pragma unroll
        for (int j = 0; j < 4; j++) {
            cp16(da + 16u * j, ag + 4 * j);
            cp16(db + 16u * j, bg + 4 * j);
        }
        asm volatile("cp.async.commit_group;" ::: "memory");
    }

    float acc[4][4][4];
    #pragma unroll
    for (int mt = 0; mt < 4; mt++)
        #pragma unroll
        for (int nt = 0; nt < 4; nt++)
            #pragma unroll
            for (int r = 0; r < 4; r++) acc[mt][nt][r] = 0.f;

    for (int kt = 0; kt < nkt; kt++) {
        const int buf = kt & 1;
        // Issue next stage before waiting on current
        if (kt + 1 < nkt) {
            const int nb = (kt + 1) & 1;
            uint32_t da = sb + (uint32_t)nb * BUF_FLOATS * 4u + sa_off;
            uint32_t db = da + (uint32_t)TILE * SSTR * 4u;
            const float* ag2 = ag + (size_t)(kt + 1) * KT;
            const float* bg2 = bg + (size_t)(kt + 1) * KT;
            #pragma unroll
            for (int j = 0; j < 4; j++) {
                cp16(da + 16u * j, ag2 + 4 * j);
                cp16(db + 16u * j, bg2 + 4 * j);
            }
            asm volatile("cp.async.commit_group;" ::: "memory");
            asm volatile("cp.async.wait_group 1;" ::: "memory");
        } else {
            asm volatile("cp.async.wait_group 0;" ::: "memory");
        }
        __syncthreads();

        const float* As = smem + buf * BUF_FLOATS;
        const float* Bs = As + TILE * SSTR;

        #pragma unroll
        for (int ks = 0; ks < 4; ks++) {
            const int kk = ks * 8 + tq;
            uint32_t af[4][4], bf[4][2];
            #pragma unroll
            for (int mt = 0; mt < 4; mt++) {
                const float* ar = As + (wm * 64 + mt * 16 + gid) * SSTR + kk;
                af[mt][0] = __float_as_uint(ar[0]);
                af[mt][1] = __float_as_uint(ar[8 * SSTR]);
                af[mt][2] = __float_as_uint(ar[4]);
                af[mt][3] = __float_as_uint(ar[8 * SSTR + 4]);
            }
            #pragma unroll
            for (int nt = 0; nt < 4; nt++) {
                const float* br = Bs + (wn * 32 + nt * 8 + gid) * SSTR + kk;
                bf[nt][0] = __float_as_uint(br[0]);
                bf[nt][1] = __float_as_uint(br[4]);
            }
            #pragma unroll
            for (int mt = 0; mt < 4; mt++)
                #pragma unroll
                for (int nt = 0; nt < 4; nt++)
                    mma_tf32(acc[mt][nt], af[mt], bf[nt]);
        }
        __syncthreads();
    }

    // Epilogue: c0,c1 at (row, 2*tq), c2,c3 at (row+8, 2*tq)
    #pragma unroll
    for (int mt = 0; mt < 4; mt++) {
        const int r0 = bm + wm * 64 + mt * 16 + gid;
        #pragma unroll
        for (int nt = 0; nt < 4; nt++) {
            const int c0 = bn + wn * 32 + nt * 8 + tq * 2;
            float v0 = acc[mt][nt][0], v1 = acc[mt][nt][1];
            float v2 = acc[mt][nt][2], v3 = acc[mt][nt][3];
            if (ROUND_C) {
                v0 = tf32r(v0); v1 = tf32r(v1); v2 = tf32r(v2); v3 = tf32r(v3);
            }
            *reinterpret_cast<float2*>(C + (size_t)r0 * ldC + c0) = make_float2(v0, v1);
            *reinterpret_cast<float2*>(C + (size_t)(r0 + 8) * ldC + c0) = make_float2(v2, v3);
        }
    }
}

// ---------------------------------------------------------------------------
// GEMM kernel wrappers
// ---------------------------------------------------------------------------
__global__ __launch_bounds__(256, 2) void qkv_tc() {
    extern __shared__ float smem[];
    const float* Bz = g_wt + (size_t)blockIdx.z * DD * DD;
    float* Cz = (blockIdx.z == 0) ? g_q : (blockIdx.z == 1) ? g_k : g_v;
    // Round outputs: they are mma operands downstream.
    tc_gemm_body<true>(g_x, Bz, Cz, DD, DD, DD, DD,
                       blockIdx.y * TILE, blockIdx.x * TILE, smem);
}

// Only lower-triangle tiles launched: grid.x = 16*17/2 = 136 per batch.
__global__ __launch_bounds__(256, 2) void scores_tc() {
    extern __shared__ float smem[];
    const int t = blockIdx.x;
    int by = (int)((sqrtf(8.f * (float)t + 1.f) - 1.f) * 0.5f);
    while ((by + 1) * (by + 2) / 2 <= t) by++;
    while (by * (by + 1) / 2 > t) by--;
    const int bx = t - by * (by + 1) / 2;
    size_t b = blockIdx.z;
    tc_gemm_body<false>(g_q + b * SS * DD, g_k + b * SS * DD,
                        g_p + b * (size_t)SS * SS, DD, DD, SS, DD,
                        by * TILE, bx * TILE, smem);
}

__global__ __launch_bounds__(256, 2) void pv_tc(float* __restrict__ out) {
    extern __shared__ float smem[];
    size_t b = blockIdx.z;
    int kmax = (int)(blockIdx.y + 1) * TILE;
    if (kmax > SS) kmax = SS;
    tc_gemm_body<false>(g_p + b * (size_t)SS * SS, g_vt + b * SS * DD,
                        out + b * SS * DD, SS, SS, DD, kmax,
                        blockIdx.y * TILE, blockIdx.x * TILE, smem);
}

// ---------------------------------------------------------------------------
// Staging: round X to tf32 once.
// ---------------------------------------------------------------------------
__global__ __launch_bounds__(256) void stage_x(const float* __restrict__ x) {
    const size_t i = ((size_t)blockIdx.x * 256 + threadIdx.x) * 4;
    float4 v = *reinterpret_cast<const float4*>(x + i);
    v.x = tf32r(v.x); v.y = tf32r(v.y); v.z = tf32r(v.z); v.w = tf32r(v.w);
    *reinterpret_cast<float4*>(g_x + i) = v;
}

// ---------------------------------------------------------------------------
// Transposes: out[c*rows + r] = op(in[r*cols + c])
// ---------------------------------------------------------------------------
template<bool ROUND>
__device__ __forceinline__ void transpose_body(
    const float* __restrict__ in, float* __restrict__ out, int rows, int cols)
{
    __shared__ float t[32][33];
    const int tx = threadIdx.x, ty = threadIdx.y;
    const int bx = blockIdx.x * 32, by = blockIdx.y * 32;
    #pragma unroll
    for (int i = 0; i < 32; i += 8) {
        float v = in[(size_t)(by + ty + i) * cols + bx + tx];
        t[ty + i][tx] = ROUND ? tf32r(v) : v;
    }
    __syncthreads();
    #pragma unroll
    for (int i = 0; i < 32; i += 8)
        out[(size_t)(bx + ty + i) * rows + by + tx] = t[tx][ty + i];
}

__global__ void transpose_w(const float* __restrict__ Wq,
                            const float* __restrict__ Wk,
                            const float* __restrict__ Wv) {
    const float* in = (blockIdx.z == 0) ? Wq : (blockIdx.z == 1) ? Wk : Wv;
    transpose_body<true>(in, g_wt + (size_t)blockIdx.z * DD * DD, DD, DD);
}

__global__ void transpose_v() {   // g_v already rounded by qkv epilogue
    size_t b = blockIdx.z;
    transpose_body<false>(g_v + b * SS * DD, g_vt + b * SS * DD, SS, DD);
}

// ---------------------------------------------------------------------------
// Causal softmax; rounds probs to tf32 at the final write.
// ---------------------------------------------------------------------------
__global__ __launch_bounds__(256) void softmax_causal()
{
    const int row = blockIdx.x;
    const int q = row & (SS - 1);
    float* srow = g_p + (size_t)row * SS;
    const int n = q + 1;
    const float inv = 0.03125f;   // 1/sqrt(1024)

    __shared__ float red[256];
    const int t = threadIdx.x;

    float m = -3.402823466e38f;
    for (int i = t; i < n; i += 256) m = fmaxf(m, srow[i]);
    red[t] = m;
    __syncthreads();
    for (int s = 128; s > 0; s >>= 1) {
        if (t < s) red[t] = fmaxf(red[t], red[t + s]);
        __syncthreads();
    }
    m = red[0] * inv;
    __syncthreads();

    float sum = 0.f;
    for (int i = t; i < n; i += 256) {
        float e = __expf(srow[i] * inv - m);
        srow[i] = e;
        sum += e;
    }
    red[t] = sum;
    __syncthreads();
    for (int s = 128; s > 0; s >>= 1) {
        if (t < s) red[t] += red[t + s];
        __syncthreads();
    }
    const float r = 1.f / red[0];
    __syncthreads();

    for (int i = t; i < n; i += 256) srow[i] = tf32r(srow[i] * r);
    for (int i = n + t; i < SS; i += 256) srow[i] = 0.f;
}

// ---------------------------------------------------------------------------
extern "C" void kernel_launch(void* const* d_in, const int* in_sizes, int n_in,
                              void* d_out, int out_size)
{
    (void)in_sizes; (void)n_in; (void)out_size;
    const float* x  = (const float*)d_in[0];
    const float* Wq = (const float*)d_in[1];
    const float* Wk = (const float*)d_in[2];
    const float* Wv = (const float*)d_in[3];
    float* out = (float*)d_out;

    cudaFuncSetAttribute(qkv_tc,    cudaFuncAttributeMaxDynamicSharedMemorySize, SMEM_BYTES);
    cudaFuncSetAttribute(scores_tc, cudaFuncAttributeMaxDynamicSharedMemorySize, SMEM_BYTES);
    cudaFuncSetAttribute(pv_tc,     cudaFuncAttributeMaxDynamicSharedMemorySize, SMEM_BYTES);

    dim3 t32(32, 8);
    stage_x<<<dim3((BB * SS * DD) / (256 * 4)), 256>>>(x);
    transpose_w<<<dim3(DD / 32, DD / 32, 3), t32>>>(Wq, Wk, Wv);
    qkv_tc<<<dim3(DD / TILE, (BB * SS) / TILE, 3), 256, SMEM_BYTES>>>();
    transpose_v<<<dim3(DD / 32, SS / 32, BB), t32>>>();
    scores_tc<<<dim3(136, 1, BB), 256, SMEM_BYTES>>>();
    softmax_causal<<<dim3(BB * SS), 256>>>();
    pv_tc<<<dim3(DD / TILE, SS / TILE, BB), 256, SMEM_BYTES>>>(out);
}

// round 5
// speedup vs baseline: 2.8287x; 1.1495x over previous
#include <cuda_runtime.h>
#include <cstdint>

// Problem constants
#define BB 4
#define SS 2048
#define DD 1024

// Scratch (allocation-free rule: __device__ globals). All tf32-pre-rounded
// except g_p scores (rounded at softmax output).
__device__ float g_x[BB * SS * DD];          // 32 MB  X rounded
__device__ float g_q[BB * SS * DD];          // 32 MB
__device__ float g_k[BB * SS * DD];          // 32 MB
__device__ float g_v[BB * SS * DD];          // 32 MB
__device__ float g_vt[BB * SS * DD];         // 32 MB (V^T per batch: [D, S])
__device__ float g_wt[3 * DD * DD];          // 12 MB (W^T: [D_out, D_in])
__device__ float g_p[(size_t)BB * SS * SS];  // 64 MB, scores -> probs in place

// ---------------------------------------------------------------------------
// tf32 mma.sync GEMM: C[M,N] = A[M,K] * B[N,K]^T, operands pre-rounded tf32.
// Block 128x128, 128 threads (4 warps of 64x64), KT=16, 3-stage cp.async.
// Fragments via ldmatrix.b16 (8x8 b16 tile == 8x4 tf32 tile; layouts match).
// Smem row stride 20 floats: ldmatrix 8-row phases hit distinct bank quads.
// ---------------------------------------------------------------------------
#define TILE 128
#define KT 16
#define STAGES 3
#define SSTR 20
#define STAGE_FLOATS (2 * TILE * SSTR)          // A+B one stage = 5120 floats
#define SMEM_BYTES (STAGES * STAGE_FLOATS * 4)  // 61440

__device__ __forceinline__ uint32_t smem_u32(const void* p) {
    uint32_t a;
    asm("{ .reg .u64 t; cvta.to.shared.u64 t, %1; cvt.u32.u64 %0, t; }"
        : "=r"(a) : "l"(p));
    return a;
}
__device__ __forceinline__ float tf32r(float x) {
    float r; asm("cvt.rna.tf32.f32 %0, %1;" : "=f"(r) : "f"(x)); return r;
}
__device__ __forceinline__ void cp16(uint32_t dst, const float* src) {
    asm volatile("cp.async.cg.shared.global [%0], [%1], 16;"
                 :: "r"(dst), "l"(src) : "memory");
}
__device__ __forceinline__ void ldsm4(uint32_t* d, uint32_t addr) {
    asm volatile("ldmatrix.sync.aligned.m8n8.x4.shared.b16 {%0,%1,%2,%3}, [%4];"
                 : "=r"(d[0]), "=r"(d[1]), "=r"(d[2]), "=r"(d[3]) : "r"(addr));
}
__device__ __forceinline__ void mma_tf32(float* c, const uint32_t* a,
                                         uint32_t b0, uint32_t b1) {
    asm volatile(
        "mma.sync.aligned.m16n8k8.row.col.f32.tf32.tf32.f32 "
        "{%0,%1,%2,%3}, {%4,%5,%6,%7}, {%8,%9}, {%0,%1,%2,%3};"
        : "+f"(c[0]), "+f"(c[1]), "+f"(c[2]), "+f"(c[3])
        : "r"(a[0]), "r"(a[1]), "r"(a[2]), "r"(a[3]), "r"(b0), "r"(b1));
}

template<bool ROUND_C>
__device__ __forceinline__ void tc_gemm_body(
    const float* __restrict__ A, const float* __restrict__ B, float* __restrict__ C,
    int ldA, int ldB, int ldC, int kmax, int bm, int bn, float* smem)
{
    const int tid = threadIdx.x;        // 0..127
    const int wid = tid >> 5;           // 0..3
    const int lid = tid & 31;
    const int gid = lid >> 2;
    const int tq  = lid & 3;
    const int wm  = wid >> 1;           // 0..1 -> 64-row half
    const int wn  = wid & 1;            // 0..1 -> 64-col half
    const uint32_t sb = smem_u32(smem);

    // cp.async loader: thread -> (row = tid>>2 (+32j), 16B chunk = tid&3)
    const int lrow = tid >> 2;
    const int lch  = tid & 3;
    const float* ag = A + (size_t)(bm + lrow) * ldA + lch * 4;
    const float* bg = B + (size_t)(bn + lrow) * ldB + lch * 4;
    const uint32_t s_off = (uint32_t)(lrow * SSTR + lch * 4) * 4u;

    const int nkt = kmax / KT;

    // Prologue: issue stages 0..STAGES-2
    #pragma unroll
    for (int s = 0; s < STAGES - 1; s++) {
        uint32_t da = sb + (uint32_t)s * STAGE_FLOATS * 4u + s_off;
        uint32_t db = da + (uint32_t)TILE * SSTR * 4u;
        const float* ag2 = ag + (size_t)s * KT;
        const float* bg2 = bg + (size_t)s * KT;
        #pragma unroll
        for (int j = 0; j < 4; j++) {
            cp16(da + (uint32_t)(32 * j * SSTR) * 4u, ag2 + (size_t)(32 * j) * ldA);
            cp16(db + (uint32_t)(32 * j * SSTR) * 4u, bg2 + (size_t)(32 * j) * ldB);
        }
        asm volatile("cp.async.commit_group;" ::: "memory");
    }

    // ldmatrix lane addressing: sub-matrix = lane>>3 -> (+8 rows if sub&1,
    // +4 k if sub&2); r = lane&7.
    const int sub = lid >> 3;
    const int rr  = lid & 7;
    const int rowsel = ((sub & 1) << 3) + rr;
    const int ksel = (sub & 2) << 1;
    const uint32_t aL = ((uint32_t)((wm * 64 + rowsel) * SSTR + ksel)) * 4u;
    const uint32_t bL = (uint32_t)TILE * SSTR * 4u +
                        ((uint32_t)((wn * 64 + rowsel) * SSTR + ksel)) * 4u;

    float acc[4][8][4];
    #pragma unroll
    for (int mt = 0; mt < 4; mt++)
        #pragma unroll
        for (int nt = 0; nt < 8; nt++)
            #pragma unroll
            for (int r = 0; r < 4; r++) acc[mt][nt][r] = 0.f;

    for (int kt = 0; kt < nkt; kt++) {
        asm volatile("cp.async.wait_group %0;" :: "n"(STAGES - 2) : "memory");
        __syncthreads();

        const uint32_t sbase = sb + (uint32_t)(kt % STAGES) * STAGE_FLOATS * 4u;
        #pragma unroll
        for (int ks = 0; ks < 2; ks++) {
            uint32_t af[4][4], bf[4][4];
            #pragma unroll
            for (int mt = 0; mt < 4; mt++)
                ldsm4(af[mt], sbase + aL + (uint32_t)(mt * 16 * SSTR) * 4u + ks * 32u);
            #pragma unroll
            for (int np = 0; np < 4; np++)
                ldsm4(bf[np], sbase + bL + (uint32_t)(np * 16 * SSTR) * 4u + ks * 32u);
            #pragma unroll
            for (int mt = 0; mt < 4; mt++)
                #pragma unroll
                for (int np = 0; np < 4; np++) {
                    mma_tf32(acc[mt][2 * np],     af[mt], bf[np][0], bf[np][2]);
                    mma_tf32(acc[mt][2 * np + 1], af[mt], bf[np][1], bf[np][3]);
                }
        }
        __syncthreads();

        if (kt + STAGES - 1 < nkt) {
            const int s = kt + STAGES - 1;
            uint32_t da = sb + (uint32_t)(s % STAGES) * STAGE_FLOATS * 4u + s_off;
            uint32_t db = da + (uint32_t)TILE * SSTR * 4u;
            const float* ag2 = ag + (size_t)s * KT;
            const float* bg2 = bg + (size_t)s * KT;
            #pragma unroll
            for (int j = 0; j < 4; j++) {
                cp16(da + (uint32_t)(32 * j * SSTR) * 4u, ag2 + (size_t)(32 * j) * ldA);
                cp16(db + (uint32_t)(32 * j * SSTR) * 4u, bg2 + (size_t)(32 * j) * ldB);
            }
        }
        asm volatile("cp.async.commit_group;" ::: "memory");
    }

    // Epilogue
    #pragma unroll
    for (int mt = 0; mt < 4; mt++) {
        const int r0 = bm + wm * 64 + mt * 16 + gid;
        #pragma unroll
        for (int nt = 0; nt < 8; nt++) {
            const int c0 = bn + wn * 64 + nt * 8 + tq * 2;
            float v0 = acc[mt][nt][0], v1 = acc[mt][nt][1];
            float v2 = acc[mt][nt][2], v3 = acc[mt][nt][3];
            if (ROUND_C) {
                v0 = tf32r(v0); v1 = tf32r(v1); v2 = tf32r(v2); v3 = tf32r(v3);
            }
            *reinterpret_cast<float2*>(C + (size_t)r0 * ldC + c0) = make_float2(v0, v1);
            *reinterpret_cast<float2*>(C + (size_t)(r0 + 8) * ldC + c0) = make_float2(v2, v3);
        }
    }
}

// ---------------------------------------------------------------------------
// GEMM kernel wrappers
// ---------------------------------------------------------------------------
__global__ __launch_bounds__(128) void qkv_tc() {
    extern __shared__ float smem[];
    const float* Bz = g_wt + (size_t)blockIdx.z * DD * DD;
    float* Cz = (blockIdx.z == 0) ? g_q : (blockIdx.z == 1) ? g_k : g_v;
    tc_gemm_body<true>(g_x, Bz, Cz, DD, DD, DD, DD,
                       blockIdx.y * TILE, blockIdx.x * TILE, smem);
}

// Only lower-triangle tiles: grid.x = 16*17/2 = 136 per batch.
__global__ __launch_bounds__(128) void scores_tc() {
    extern __shared__ float smem[];
    const int t = blockIdx.x;
    int by = (int)((sqrtf(8.f * (float)t + 1.f) - 1.f) * 0.5f);
    while ((by + 1) * (by + 2) / 2 <= t) by++;
    while (by * (by + 1) / 2 > t) by--;
    const int bx = t - by * (by + 1) / 2;
    size_t b = blockIdx.z;
    tc_gemm_body<false>(g_q + b * SS * DD, g_k + b * SS * DD,
                        g_p + b * (size_t)SS * SS, DD, DD, SS, DD,
                        by * TILE, bx * TILE, smem);
}

__global__ __launch_bounds__(128) void pv_tc(float* __restrict__ out) {
    extern __shared__ float smem[];
    size_t b = blockIdx.z;
    int kmax = (int)(blockIdx.y + 1) * TILE;
    if (kmax > SS) kmax = SS;
    tc_gemm_body<false>(g_p + b * (size_t)SS * SS, g_vt + b * SS * DD,
                        out + b * SS * DD, SS, SS, DD, kmax,
                        blockIdx.y * TILE, blockIdx.x * TILE, smem);
}

// ---------------------------------------------------------------------------
// Staging: round X to tf32 once.
// ---------------------------------------------------------------------------
__global__ __launch_bounds__(256) void stage_x(const float* __restrict__ x) {
    const size_t i = ((size_t)blockIdx.x * 256 + threadIdx.x) * 4;
    float4 v = *reinterpret_cast<const float4*>(x + i);
    v.x = tf32r(v.x); v.y = tf32r(v.y); v.z = tf32r(v.z); v.w = tf32r(v.w);
    *reinterpret_cast<float4*>(g_x + i) = v;
}

// ---------------------------------------------------------------------------
// Transposes: out[c*rows + r] = op(in[r*cols + c])
// ---------------------------------------------------------------------------
template<bool ROUND>
__device__ __forceinline__ void transpose_body(
    const float* __restrict__ in, float* __restrict__ out, int rows, int cols)
{
    __shared__ float t[32][33];
    const int tx = threadIdx.x, ty = threadIdx.y;
    const int bx = blockIdx.x * 32, by = blockIdx.y * 32;
    #pragma unroll
    for (int i = 0; i < 32; i += 8) {
        float v = in[(size_t)(by + ty + i) * cols + bx + tx];
        t[ty + i][tx] = ROUND ? tf32r(v) : v;
    }
    __syncthreads();
    #pragma unroll
    for (int i = 0; i < 32; i += 8)
        out[(size_t)(bx + ty + i) * rows + by + tx] = t[tx][ty + i];
}

__global__ void transpose_w(const float* __restrict__ Wq,
                            const float* __restrict__ Wk,
                            const float* __restrict__ Wv) {
    const float* in = (blockIdx.z == 0) ? Wq : (blockIdx.z == 1) ? Wk : Wv;
    transpose_body<true>(in, g_wt + (size_t)blockIdx.z * DD * DD, DD, DD);
}

__global__ void transpose_v() {   // g_v already rounded by qkv epilogue
    size_t b = blockIdx.z;
    transpose_body<false>(g_v + b * SS * DD, g_vt + b * SS * DD, SS, DD);
}

// ---------------------------------------------------------------------------
// Causal softmax; rounds probs to tf32 at the final write.
// ---------------------------------------------------------------------------
__global__ __launch_bounds__(256) void softmax_causal()
{
    const int row = blockIdx.x;
    const int q = row & (SS - 1);
    float* srow = g_p + (size_t)row * SS;
    const int n = q + 1;
    const float inv = 0.03125f;   // 1/sqrt(1024)

    __shared__ float red[256];
    const int t = threadIdx.x;

    float m = -3.402823466e38f;
    for (int i = t; i < n; i += 256) m = fmaxf(m, srow[i]);
    red[t] = m;
    __syncthreads();
    for (int s = 128; s > 0; s >>= 1) {
        if (t < s) red[t] = fmaxf(red[t], red[t + s]);
        __syncthreads();
    }
    m = red[0] * inv;
    __syncthreads();

    float sum = 0.f;
    for (int i = t; i < n; i += 256) {
        float e = __expf(srow[i] * inv - m);
        srow[i] = e;
        sum += e;
    }
    red[t] = sum;
    __syncthreads();
    for (int s = 128; s > 0; s >>= 1) {
        if (t < s) red[t] += red[t + s];
        __syncthreads();
    }
    const float r = 1.f / red[0];
    __syncthreads();

    for (int i = t; i < n; i += 256) srow[i] = tf32r(srow[i] * r);
    for (int i = n + t; i < SS; i += 256) srow[i] = 0.f;
}

// ---------------------------------------------------------------------------
extern "C" void kernel_launch(void* const* d_in, const int* in_sizes, int n_in,
                              void* d_out, int out_size)
{
    (void)in_sizes; (void)n_in; (void)out_size;
    const float* x  = (const float*)d_in[0];
    const float* Wq = (const float*)d_in[1];
    const float* Wk = (const float*)d_in[2];
    const float* Wv = (const float*)d_in[3];
    float* out = (float*)d_out;

    cudaFuncSetAttribute(qkv_tc,    cudaFuncAttributeMaxDynamicSharedMemorySize, SMEM_BYTES);
    cudaFuncSetAttribute(scores_tc, cudaFuncAttributeMaxDynamicSharedMemorySize, SMEM_BYTES);
    cudaFuncSetAttribute(pv_tc,     cudaFuncAttributeMaxDynamicSharedMemorySize, SMEM_BYTES);

    dim3 t32(32, 8);
    stage_x<<<dim3((BB * SS * DD) / (256 * 4)), 256>>>(x);
    transpose_w<<<dim3(DD / 32, DD / 32, 3), t32>>>(Wq, Wk, Wv);
    qkv_tc<<<dim3(DD / TILE, (BB * SS) / TILE, 3), 128, SMEM_BYTES>>>();
    transpose_v<<<dim3(DD / 32, SS / 32, BB), t32>>>();
    scores_tc<<<dim3(136, 1, BB), 128, SMEM_BYTES>>>();
    softmax_causal<<<dim3(BB * SS), 256>>>();
    pv_tc<<<dim3(DD / TILE, SS / TILE, BB), 128, SMEM_BYTES>>>(out);
}

// round 6
// speedup vs baseline: 3.0589x; 1.0814x over previous
#include <cuda_runtime.h>
#include <cstdint>

// Problem constants
#define BB 4
#define SS 2048
#define DD 1024

// Scratch (allocation-free rule: __device__ globals). All tf32-pre-rounded
// except g_p scores (rounded at softmax output).
__device__ float g_x[BB * SS * DD];          // 32 MB  X rounded
__device__ float g_q[BB * SS * DD];          // 32 MB
__device__ float g_k[BB * SS * DD];          // 32 MB
__device__ float g_v[BB * SS * DD];          // 32 MB
__device__ float g_vt[BB * SS * DD];         // 32 MB (V^T per batch: [D, S])
__device__ float g_wt[3 * DD * DD];          // 12 MB (W^T: [D_out, D_in])
__device__ float g_p[(size_t)BB * SS * SS];  // 64 MB, scores -> probs in place

// ---------------------------------------------------------------------------
// tf32 mma.sync GEMM: C[M,N] = A[M,K] * B[N,K]^T, operands pre-rounded tf32.
// Block 128x128, 128 threads (4 warps of 64x64), KT=16, 4-stage cp.async,
// single __syncthreads per k-tile, prefetch distance 3.
// Fragments via ldmatrix.b16 (8x8 b16 tile == 8x4 tf32 tile; layouts match).
// Smem row stride 20 floats: ldmatrix 8-row phases cover all 32 banks.
// ---------------------------------------------------------------------------
#define TILE 128
#define KT 16
#define STAGES 4
#define SSTR 20
#define STAGE_FLOATS (2 * TILE * SSTR)          // A+B one stage = 5120 floats
#define SMEM_BYTES (STAGES * STAGE_FLOATS * 4)  // 81920

__device__ __forceinline__ uint32_t smem_u32(const void* p) {
    uint32_t a;
    asm("{ .reg .u64 t; cvta.to.shared.u64 t, %1; cvt.u32.u64 %0, t; }"
        : "=r"(a) : "l"(p));
    return a;
}
__device__ __forceinline__ float tf32r(float x) {
    float r; asm("cvt.rna.tf32.f32 %0, %1;" : "=f"(r) : "f"(x)); return r;
}
__device__ __forceinline__ void cp16(uint32_t dst, const float* src) {
    asm volatile("cp.async.cg.shared.global [%0], [%1], 16;"
                 :: "r"(dst), "l"(src) : "memory");
}
__device__ __forceinline__ void ldsm4(uint32_t* d, uint32_t addr) {
    asm volatile("ldmatrix.sync.aligned.m8n8.x4.shared.b16 {%0,%1,%2,%3}, [%4];"
                 : "=r"(d[0]), "=r"(d[1]), "=r"(d[2]), "=r"(d[3]) : "r"(addr));
}
__device__ __forceinline__ void mma_tf32(float* c, const uint32_t* a,
                                         uint32_t b0, uint32_t b1) {
    asm volatile(
        "mma.sync.aligned.m16n8k8.row.col.f32.tf32.tf32.f32 "
        "{%0,%1,%2,%3}, {%4,%5,%6,%7}, {%8,%9}, {%0,%1,%2,%3};"
        : "+f"(c[0]), "+f"(c[1]), "+f"(c[2]), "+f"(c[3])
        : "r"(a[0]), "r"(a[1]), "r"(a[2]), "r"(a[3]), "r"(b0), "r"(b1));
}

template<bool ROUND_C>
__device__ __forceinline__ void tc_gemm_body(
    const float* __restrict__ A, const float* __restrict__ B, float* __restrict__ C,
    int ldA, int ldB, int ldC, int kmax, int bm, int bn, float* smem)
{
    const int tid = threadIdx.x;        // 0..127
    const int wid = tid >> 5;           // 0..3
    const int lid = tid & 31;
    const int gid = lid >> 2;
    const int tq  = lid & 3;
    const int wm  = wid >> 1;           // 0..1 -> 64-row half
    const int wn  = wid & 1;            // 0..1 -> 64-col half
    const uint32_t sb = smem_u32(smem);

    // cp.async loader: thread -> (row = tid>>2 (+32j), 16B chunk = tid&3)
    const int lrow = tid >> 2;
    const int lch  = tid & 3;
    const float* ag = A + (size_t)(bm + lrow) * ldA + lch * 4;
    const float* bg = B + (size_t)(bn + lrow) * ldB + lch * 4;
    const uint32_t s_off = (uint32_t)(lrow * SSTR + lch * 4) * 4u;

    const int nkt = kmax / KT;   // >= 8 always

    // Prologue: issue stages 0..STAGES-2 (3 groups in flight)
    #pragma unroll
    for (int s = 0; s < STAGES - 1; s++) {
        uint32_t da = sb + (uint32_t)s * STAGE_FLOATS * 4u + s_off;
        uint32_t db = da + (uint32_t)TILE * SSTR * 4u;
        const float* ag2 = ag + (size_t)s * KT;
        const float* bg2 = bg + (size_t)s * KT;
        #pragma unroll
        for (int j = 0; j < 4; j++) {
            cp16(da + (uint32_t)(32 * j * SSTR) * 4u, ag2 + (size_t)(32 * j) * ldA);
            cp16(db + (uint32_t)(32 * j * SSTR) * 4u, bg2 + (size_t)(32 * j) * ldB);
        }
        asm volatile("cp.async.commit_group;" ::: "memory");
    }

    // ldmatrix lane addressing
    const int sub = lid >> 3;
    const int rr  = lid & 7;
    const int rowsel = ((sub & 1) << 3) + rr;
    const int ksel = (sub & 2) << 1;
    const uint32_t aL = ((uint32_t)((wm * 64 + rowsel) * SSTR + ksel)) * 4u;
    const uint32_t bL = (uint32_t)TILE * SSTR * 4u +
                        ((uint32_t)((wn * 64 + rowsel) * SSTR + ksel)) * 4u;

    float acc[4][8][4];
    #pragma unroll
    for (int mt = 0; mt < 4; mt++)
        #pragma unroll
        for (int nt = 0; nt < 8; nt++)
            #pragma unroll
            for (int r = 0; r < 4; r++) acc[mt][nt][r] = 0.f;

    for (int kt = 0; kt < nkt; kt++) {
        // Stage kt complete when <= STAGES-2 groups pending.
        asm volatile("cp.async.wait_group %0;" :: "n"(STAGES - 2) : "memory");
        __syncthreads();   // also orders prior reads of stage (kt-1)%STAGES

        // Issue-early: prefetch stage kt+STAGES-1 before compute.
        if (kt + STAGES - 1 < nkt) {
            const int s = kt + STAGES - 1;
            uint32_t da = sb + (uint32_t)(s % STAGES) * STAGE_FLOATS * 4u + s_off;
            uint32_t db = da + (uint32_t)TILE * SSTR * 4u;
            const float* ag2 = ag + (size_t)s * KT;
            const float* bg2 = bg + (size_t)s * KT;
            #pragma unroll
            for (int j = 0; j < 4; j++) {
                cp16(da + (uint32_t)(32 * j * SSTR) * 4u, ag2 + (size_t)(32 * j) * ldA);
                cp16(db + (uint32_t)(32 * j * SSTR) * 4u, bg2 + (size_t)(32 * j) * ldB);
            }
        }
        asm volatile("cp.async.commit_group;" ::: "memory");

        const uint32_t sbase = sb + (uint32_t)(kt % STAGES) * STAGE_FLOATS * 4u;
        #pragma unroll
        for (int ks = 0; ks < 2; ks++) {
            uint32_t af[4][4], bf[4][4];
            #pragma unroll
            for (int mt = 0; mt < 4; mt++)
                ldsm4(af[mt], sbase + aL + (uint32_t)(mt * 16 * SSTR) * 4u + ks * 32u);
            #pragma unroll
            for (int np = 0; np < 4; np++)
                ldsm4(bf[np], sbase + bL + (uint32_t)(np * 16 * SSTR) * 4u + ks * 32u);
            #pragma unroll
            for (int mt = 0; mt < 4; mt++)
                #pragma unroll
                for (int np = 0; np < 4; np++) {
                    mma_tf32(acc[mt][2 * np],     af[mt], bf[np][0], bf[np][2]);
                    mma_tf32(acc[mt][2 * np + 1], af[mt], bf[np][1], bf[np][3]);
                }
        }
    }

    // Epilogue
    #pragma unroll
    for (int mt = 0; mt < 4; mt++) {
        const int r0 = bm + wm * 64 + mt * 16 + gid;
        #pragma unroll
        for (int nt = 0; nt < 8; nt++) {
            const int c0 = bn + wn * 64 + nt * 8 + tq * 2;
            float v0 = acc[mt][nt][0], v1 = acc[mt][nt][1];
            float v2 = acc[mt][nt][2], v3 = acc[mt][nt][3];
            if (ROUND_C) {
                v0 = tf32r(v0); v1 = tf32r(v1); v2 = tf32r(v2); v3 = tf32r(v3);
            }
            *reinterpret_cast<float2*>(C + (size_t)r0 * ldC + c0) = make_float2(v0, v1);
            *reinterpret_cast<float2*>(C + (size_t)(r0 + 8) * ldC + c0) = make_float2(v2, v3);
        }
    }
}

// ---------------------------------------------------------------------------
// GEMM kernel wrappers
// ---------------------------------------------------------------------------
__global__ __launch_bounds__(128, 2) void qkv_tc() {
    extern __shared__ float smem[];
    const float* Bz = g_wt + (size_t)blockIdx.z * DD * DD;
    float* Cz = (blockIdx.z == 0) ? g_q : (blockIdx.z == 1) ? g_k : g_v;
    tc_gemm_body<true>(g_x, Bz, Cz, DD, DD, DD, DD,
                       blockIdx.y * TILE, blockIdx.x * TILE, smem);
}

// Only lower-triangle tiles: grid.x = 16*17/2 = 136 per batch.
__global__ __launch_bounds__(128, 2) void scores_tc() {
    extern __shared__ float smem[];
    const int t = blockIdx.x;
    int by = (int)((sqrtf(8.f * (float)t + 1.f) - 1.f) * 0.5f);
    while ((by + 1) * (by + 2) / 2 <= t) by++;
    while (by * (by + 1) / 2 > t) by--;
    const int bx = t - by * (by + 1) / 2;
    size_t b = blockIdx.z;
    tc_gemm_body<false>(g_q + b * SS * DD, g_k + b * SS * DD,
                        g_p + b * (size_t)SS * SS, DD, DD, SS, DD,
                        by * TILE, bx * TILE, smem);
}

__global__ __launch_bounds__(128, 2) void pv_tc(float* __restrict__ out) {
    extern __shared__ float smem[];
    size_t b = blockIdx.z;
    // Heavy-first: reverse block-row order so large-kmax tiles start in wave 1.
    const int byt = (int)gridDim.y - 1 - (int)blockIdx.y;
    int kmax = (byt + 1) * TILE;
    if (kmax > SS) kmax = SS;
    tc_gemm_body<false>(g_p + b * (size_t)SS * SS, g_vt + b * SS * DD,
                        out + b * SS * DD, SS, SS, DD, kmax,
                        byt * TILE, blockIdx.x * TILE, smem);
}

// ---------------------------------------------------------------------------
// Staging: round X to tf32 once.
// ---------------------------------------------------------------------------
__global__ __launch_bounds__(256) void stage_x(const float* __restrict__ x) {
    const size_t i = ((size_t)blockIdx.x * 256 + threadIdx.x) * 4;
    float4 v = *reinterpret_cast<const float4*>(x + i);
    v.x = tf32r(v.x); v.y = tf32r(v.y); v.z = tf32r(v.z); v.w = tf32r(v.w);
    *reinterpret_cast<float4*>(g_x + i) = v;
}

// ---------------------------------------------------------------------------
// Transposes: out[c*rows + r] = op(in[r*cols + c])
// ---------------------------------------------------------------------------
template<bool ROUND>
__device__ __forceinline__ void transpose_body(
    const float* __restrict__ in, float* __restrict__ out, int rows, int cols)
{
    __shared__ float t[32][33];
    const int tx = threadIdx.x, ty = threadIdx.y;
    const int bx = blockIdx.x * 32, by = blockIdx.y * 32;
    #pragma unroll
    for (int i = 0; i < 32; i += 8) {
        float v = in[(size_t)(by + ty + i) * cols + bx + tx];
        t[ty + i][tx] = ROUND ? tf32r(v) : v;
    }
    __syncthreads();
    #pragma unroll
    for (int i = 0; i < 32; i += 8)
        out[(size_t)(bx + ty + i) * rows + by + tx] = t[tx][ty + i];
}

__global__ void transpose_w(const float* __restrict__ Wq,
                            const float* __restrict__ Wk,
                            const float* __restrict__ Wv) {
    const float* in = (blockIdx.z == 0) ? Wq : (blockIdx.z == 1) ? Wk : Wv;
    transpose_body<true>(in, g_wt + (size_t)blockIdx.z * DD * DD, DD, DD);
}

__global__ void transpose_v() {   // g_v already rounded by qkv epilogue
    size_t b = blockIdx.z;
    transpose_body<false>(g_v + b * SS * DD, g_vt + b * SS * DD, SS, DD);
}

// ---------------------------------------------------------------------------
// Causal softmax; rounds probs to tf32 at the final write.
// ---------------------------------------------------------------------------
__global__ __launch_bounds__(256) void softmax_causal()
{
    const int row = blockIdx.x;
    const int q = row & (SS - 1);
    float* srow = g_p + (size_t)row * SS;
    const int n = q + 1;
    const float inv = 0.03125f;   // 1/sqrt(1024)

    __shared__ float red[256];
    const int t = threadIdx.x;

    float m = -3.402823466e38f;
    for (int i = t; i < n; i += 256) m = fmaxf(m, srow[i]);
    red[t] = m;
    __syncthreads();
    for (int s = 128; s > 0; s >>= 1) {
        if (t < s) red[t] = fmaxf(red[t], red[t + s]);
        __syncthreads();
    }
    m = red[0] * inv;
    __syncthreads();

    float sum = 0.f;
    for (int i = t; i < n; i += 256) {
        float e = __expf(srow[i] * inv - m);
        srow[i] = e;
        sum += e;
    }
    red[t] = sum;
    __syncthreads();
    for (int s = 128; s > 0; s >>= 1) {
        if (t < s) red[t] += red[t + s];
        __syncthreads();
    }
    const float r = 1.f / red[0];
    __syncthreads();

    for (int i = t; i < n; i += 256) srow[i] = tf32r(srow[i] * r);
    for (int i = n + t; i < SS; i += 256) srow[i] = 0.f;
}

// ---------------------------------------------------------------------------
extern "C" void kernel_launch(void* const* d_in, const int* in_sizes, int n_in,
                              void* d_out, int out_size)
{
    (void)in_sizes; (void)n_in; (void)out_size;
    const float* x  = (const float*)d_in[0];
    const float* Wq = (const float*)d_in[1];
    const float* Wk = (const float*)d_in[2];
    const float* Wv = (const float*)d_in[3];
    float* out = (float*)d_out;

    cudaFuncSetAttribute(qkv_tc,    cudaFuncAttributeMaxDynamicSharedMemorySize, SMEM_BYTES);
    cudaFuncSetAttribute(scores_tc, cudaFuncAttributeMaxDynamicSharedMemorySize, SMEM_BYTES);
    cudaFuncSetAttribute(pv_tc,     cudaFuncAttributeMaxDynamicSharedMemorySize, SMEM_BYTES);

    dim3 t32(32, 8);
    stage_x<<<dim3((BB * SS * DD) / (256 * 4)), 256>>>(x);
    transpose_w<<<dim3(DD / 32, DD / 32, 3), t32>>>(Wq, Wk, Wv);
    qkv_tc<<<dim3(DD / TILE, (BB * SS) / TILE, 3), 128, SMEM_BYTES>>>();
    transpose_v<<<dim3(DD / 32, SS / 32, BB), t32>>>();
    scores_tc<<<dim3(136, 1, BB), 128, SMEM_BYTES>>>();
    softmax_causal<<<dim3(BB * SS), 256>>>();
    pv_tc<<<dim3(DD / TILE, SS / TILE, BB), 128, SMEM_BYTES>>>(out);
}

// round 7
// speedup vs baseline: 3.7240x; 1.2174x over previous
#include <cuda_runtime.h>
#include <cstdint>

// Problem constants
#define BB 4
#define SS 2048
#define DD 1024

// Scratch (allocation-free rule: __device__ globals). All tf32-pre-rounded
// except g_p scores (rounded at softmax output).
__device__ float g_x[BB * SS * DD];          // 32 MB  X rounded
__device__ float g_q[BB * SS * DD];          // 32 MB
__device__ float g_k[BB * SS * DD];          // 32 MB
__device__ float g_v[BB * SS * DD];          // 32 MB
__device__ float g_vt[BB * SS * DD];         // 32 MB (V^T per batch: [D, S])
__device__ float g_wt[3 * DD * DD];          // 12 MB (W^T: [D_out, D_in])
__device__ float g_p[(size_t)BB * SS * SS];  // 64 MB, scores -> probs in place

// ---------------------------------------------------------------------------
// tf32 mma.sync GEMM: C[M,N] = A[M,K] * B[N,K]^T, operands pre-rounded tf32.
// Block 128x128, 256 threads (8 warps of 32x64), KT=16, 4-stage cp.async,
// single __syncthreads per k-tile, prefetch distance 3.
// 8 warps -> 4 per SMSP at 2 CTAs/SM: latency hiding pool doubled vs 64x64.
// Fragments via ldmatrix.b16 (8x8 b16 tile == 8x4 tf32 tile; layouts match).
// Smem row stride 20 floats: ldmatrix 8-row phases cover distinct bank quads.
// ---------------------------------------------------------------------------
#define TILE 128
#define KT 16
#define STAGES 4
#define SSTR 20
#define STAGE_FLOATS (2 * TILE * SSTR)          // A+B one stage = 5120 floats
#define SMEM_BYTES (STAGES * STAGE_FLOATS * 4)  // 81920

__device__ __forceinline__ uint32_t smem_u32(const void* p) {
    uint32_t a;
    asm("{ .reg .u64 t; cvta.to.shared.u64 t, %1; cvt.u32.u64 %0, t; }"
        : "=r"(a) : "l"(p));
    return a;
}
__device__ __forceinline__ float tf32r(float x) {
    float r; asm("cvt.rna.tf32.f32 %0, %1;" : "=f"(r) : "f"(x)); return r;
}
__device__ __forceinline__ void cp16(uint32_t dst, const float* src) {
    asm volatile("cp.async.cg.shared.global [%0], [%1], 16;"
                 :: "r"(dst), "l"(src) : "memory");
}
__device__ __forceinline__ void ldsm4(uint32_t* d, uint32_t addr) {
    asm volatile("ldmatrix.sync.aligned.m8n8.x4.shared.b16 {%0,%1,%2,%3}, [%4];"
                 : "=r"(d[0]), "=r"(d[1]), "=r"(d[2]), "=r"(d[3]) : "r"(addr));
}
__device__ __forceinline__ void mma_tf32(float* c, const uint32_t* a,
                                         uint32_t b0, uint32_t b1) {
    asm volatile(
        "mma.sync.aligned.m16n8k8.row.col.f32.tf32.tf32.f32 "
        "{%0,%1,%2,%3}, {%4,%5,%6,%7}, {%8,%9}, {%0,%1,%2,%3};"
        : "+f"(c[0]), "+f"(c[1]), "+f"(c[2]), "+f"(c[3])
        : "r"(a[0]), "r"(a[1]), "r"(a[2]), "r"(a[3]), "r"(b0), "r"(b1));
}

template<bool ROUND_C>
__device__ __forceinline__ void tc_gemm_body(
    const float* __restrict__ A, const float* __restrict__ B, float* __restrict__ C,
    int ldA, int ldB, int ldC, int kmax, int bm, int bn, float* smem)
{
    const int tid = threadIdx.x;        // 0..255
    const int wid = tid >> 5;           // 0..7
    const int lid = tid & 31;
    const int gid = lid >> 2;
    const int tq  = lid & 3;
    const int wm  = wid >> 1;           // 0..3 -> 32-row slice
    const int wn  = wid & 1;            // 0..1 -> 64-col half
    const uint32_t sb = smem_u32(smem);

    // cp.async loader: thread -> (row = tid>>2 (+64j), 16B chunk = tid&3)
    const int lrow = tid >> 2;          // 0..63
    const int lch  = tid & 3;
    const float* ag = A + (size_t)(bm + lrow) * ldA + lch * 4;
    const float* bg = B + (size_t)(bn + lrow) * ldB + lch * 4;
    const uint32_t s_off = (uint32_t)(lrow * SSTR + lch * 4) * 4u;

    const int nkt = kmax / KT;   // >= 8 always

    // Prologue: issue stages 0..STAGES-2 (3 groups in flight)
    #pragma unroll
    for (int s = 0; s < STAGES - 1; s++) {
        uint32_t da = sb + (uint32_t)s * STAGE_FLOATS * 4u + s_off;
        uint32_t db = da + (uint32_t)TILE * SSTR * 4u;
        const float* ag2 = ag + (size_t)s * KT;
        const float* bg2 = bg + (size_t)s * KT;
        #pragma unroll
        for (int j = 0; j < 2; j++) {
            cp16(da + (uint32_t)(64 * j * SSTR) * 4u, ag2 + (size_t)(64 * j) * ldA);
            cp16(db + (uint32_t)(64 * j * SSTR) * 4u, bg2 + (size_t)(64 * j) * ldB);
        }
        asm volatile("cp.async.commit_group;" ::: "memory");
    }

    // ldmatrix lane addressing
    const int sub = lid >> 3;
    const int rr  = lid & 7;
    const int rowsel = ((sub & 1) << 3) + rr;
    const int ksel = (sub & 2) << 1;
    const uint32_t aL = ((uint32_t)((wm * 32 + rowsel) * SSTR + ksel)) * 4u;
    const uint32_t bL = (uint32_t)TILE * SSTR * 4u +
                        ((uint32_t)((wn * 64 + rowsel) * SSTR + ksel)) * 4u;

    float acc[2][8][4];
    #pragma unroll
    for (int mt = 0; mt < 2; mt++)
        #pragma unroll
        for (int nt = 0; nt < 8; nt++)
            #pragma unroll
            for (int r = 0; r < 4; r++) acc[mt][nt][r] = 0.f;

    for (int kt = 0; kt < nkt; kt++) {
        // Stage kt complete when <= STAGES-2 groups pending.
        asm volatile("cp.async.wait_group %0;" :: "n"(STAGES - 2) : "memory");
        __syncthreads();   // also orders prior reads of stage (kt-1)%STAGES

        // Issue-early: prefetch stage kt+STAGES-1 before compute.
        if (kt + STAGES - 1 < nkt) {
            const int s = kt + STAGES - 1;
            uint32_t da = sb + (uint32_t)(s % STAGES) * STAGE_FLOATS * 4u + s_off;
            uint32_t db = da + (uint32_t)TILE * SSTR * 4u;
            const float* ag2 = ag + (size_t)s * KT;
            const float* bg2 = bg + (size_t)s * KT;
            #pragma unroll
            for (int j = 0; j < 2; j++) {
                cp16(da + (uint32_t)(64 * j * SSTR) * 4u, ag2 + (size_t)(64 * j) * ldA);
                cp16(db + (uint32_t)(64 * j * SSTR) * 4u, bg2 + (size_t)(64 * j) * ldB);
            }
        }
        asm volatile("cp.async.commit_group;" ::: "memory");

        const uint32_t sbase = sb + (uint32_t)(kt % STAGES) * STAGE_FLOATS * 4u;
        #pragma unroll
        for (int ks = 0; ks < 2; ks++) {
            uint32_t af[2][4], bf[4][4];
            #pragma unroll
            for (int mt = 0; mt < 2; mt++)
                ldsm4(af[mt], sbase + aL + (uint32_t)(mt * 16 * SSTR) * 4u + ks * 32u);
            #pragma unroll
            for (int np = 0; np < 4; np++)
                ldsm4(bf[np], sbase + bL + (uint32_t)(np * 16 * SSTR) * 4u + ks * 32u);
            #pragma unroll
            for (int mt = 0; mt < 2; mt++)
                #pragma unroll
                for (int np = 0; np < 4; np++) {
                    mma_tf32(acc[mt][2 * np],     af[mt], bf[np][0], bf[np][2]);
                    mma_tf32(acc[mt][2 * np + 1], af[mt], bf[np][1], bf[np][3]);
                }
        }
    }

    // Epilogue
    #pragma unroll
    for (int mt = 0; mt < 2; mt++) {
        const int r0 = bm + wm * 32 + mt * 16 + gid;
        #pragma unroll
        for (int nt = 0; nt < 8; nt++) {
            const int c0 = bn + wn * 64 + nt * 8 + tq * 2;
            float v0 = acc[mt][nt][0], v1 = acc[mt][nt][1];
            float v2 = acc[mt][nt][2], v3 = acc[mt][nt][3];
            if (ROUND_C) {
                v0 = tf32r(v0); v1 = tf32r(v1); v2 = tf32r(v2); v3 = tf32r(v3);
            }
            *reinterpret_cast<float2*>(C + (size_t)r0 * ldC + c0) = make_float2(v0, v1);
            *reinterpret_cast<float2*>(C + (size_t)(r0 + 8) * ldC + c0) = make_float2(v2, v3);
        }
    }
}

// ---------------------------------------------------------------------------
// GEMM kernel wrappers
// ---------------------------------------------------------------------------
__global__ __launch_bounds__(256, 2) void qkv_tc() {
    extern __shared__ float smem[];
    const float* Bz = g_wt + (size_t)blockIdx.z * DD * DD;
    float* Cz = (blockIdx.z == 0) ? g_q : (blockIdx.z == 1) ? g_k : g_v;
    tc_gemm_body<true>(g_x, Bz, Cz, DD, DD, DD, DD,
                       blockIdx.y * TILE, blockIdx.x * TILE, smem);
}

// Only lower-triangle tiles: grid.x = 16*17/2 = 136 per batch.
__global__ __launch_bounds__(256, 2) void scores_tc() {
    extern __shared__ float smem[];
    const int t = blockIdx.x;
    int by = (int)((sqrtf(8.f * (float)t + 1.f) - 1.f) * 0.5f);
    while ((by + 1) * (by + 2) / 2 <= t) by++;
    while (by * (by + 1) / 2 > t) by--;
    const int bx = t - by * (by + 1) / 2;
    size_t b = blockIdx.z;
    tc_gemm_body<false>(g_q + b * SS * DD, g_k + b * SS * DD,
                        g_p + b * (size_t)SS * SS, DD, DD, SS, DD,
                        by * TILE, bx * TILE, smem);
}

__global__ __launch_bounds__(256, 2) void pv_tc(float* __restrict__ out) {
    extern __shared__ float smem[];
    size_t b = blockIdx.z;
    // Heavy-first: reverse block-row order so large-kmax tiles start in wave 1.
    const int byt = (int)gridDim.y - 1 - (int)blockIdx.y;
    int kmax = (byt + 1) * TILE;
    if (kmax > SS) kmax = SS;
    tc_gemm_body<false>(g_p + b * (size_t)SS * SS, g_vt + b * SS * DD,
                        out + b * SS * DD, SS, SS, DD, kmax,
                        byt * TILE, blockIdx.x * TILE, smem);
}

// ---------------------------------------------------------------------------
// Staging: round X to tf32 once.
// ---------------------------------------------------------------------------
__global__ __launch_bounds__(256) void stage_x(const float* __restrict__ x) {
    const size_t i = ((size_t)blockIdx.x * 256 + threadIdx.x) * 4;
    float4 v = *reinterpret_cast<const float4*>(x + i);
    v.x = tf32r(v.x); v.y = tf32r(v.y); v.z = tf32r(v.z); v.w = tf32r(v.w);
    *reinterpret_cast<float4*>(g_x + i) = v;
}

// ---------------------------------------------------------------------------
// Transposes: out[c*rows + r] = op(in[r*cols + c])
// ---------------------------------------------------------------------------
template<bool ROUND>
__device__ __forceinline__ void transpose_body(
    const float* __restrict__ in, float* __restrict__ out, int rows, int cols)
{
    __shared__ float t[32][33];
    const int tx = threadIdx.x, ty = threadIdx.y;
    const int bx = blockIdx.x * 32, by = blockIdx.y * 32;
    #pragma unroll
    for (int i = 0; i < 32; i += 8) {
        float v = in[(size_t)(by + ty + i) * cols + bx + tx];
        t[ty + i][tx] = ROUND ? tf32r(v) : v;
    }
    __syncthreads();
    #pragma unroll
    for (int i = 0; i < 32; i += 8)
        out[(size_t)(bx + ty + i) * rows + by + tx] = t[tx][ty + i];
}

__global__ void transpose_w(const float* __restrict__ Wq,
                            const float* __restrict__ Wk,
                            const float* __restrict__ Wv) {
    const float* in = (blockIdx.z == 0) ? Wq : (blockIdx.z == 1) ? Wk : Wv;
    transpose_body<true>(in, g_wt + (size_t)blockIdx.z * DD * DD, DD, DD);
}

__global__ void transpose_v() {   // g_v already rounded by qkv epilogue
    size_t b = blockIdx.z;
    transpose_body<false>(g_v + b * SS * DD, g_vt + b * SS * DD, SS, DD);
}

// ---------------------------------------------------------------------------
// Causal softmax; rounds probs to tf32 at the final write. Zeroes only the
// masked tail inside this row's diagonal 128-block: pv_tc's kmax clamp never
// reads beyond it.
// ---------------------------------------------------------------------------
__global__ __launch_bounds__(256) void softmax_causal()
{
    const int row = blockIdx.x;
    const int q = row & (SS - 1);
    float* srow = g_p + (size_t)row * SS;
    const int n = q + 1;
    const int kend = ((q >> 7) + 1) << 7;   // end of diagonal 128-block
    const float inv = 0.03125f;   // 1/sqrt(1024)

    __shared__ float red[256];
    const int t = threadIdx.x;

    float m = -3.402823466e38f;
    for (int i = t; i < n; i += 256) m = fmaxf(m, srow[i]);
    red[t] = m;
    __syncthreads();
    for (int s = 128; s > 0; s >>= 1) {
        if (t < s) red[t] = fmaxf(red[t], red[t + s]);
        __syncthreads();
    }
    m = red[0] * inv;
    __syncthreads();

    float sum = 0.f;
    for (int i = t; i < n; i += 256) {
        float e = __expf(srow[i] * inv - m);
        srow[i] = e;
        sum += e;
    }
    red[t] = sum;
    __syncthreads();
    for (int s = 128; s > 0; s >>= 1) {
        if (t < s) red[t] += red[t + s];
        __syncthreads();
    }
    const float r = 1.f / red[0];
    __syncthreads();

    for (int i = t; i < n; i += 256) srow[i] = tf32r(srow[i] * r);
    for (int i = n + t; i < kend; i += 256) srow[i] = 0.f;
}

// ---------------------------------------------------------------------------
extern "C" void kernel_launch(void* const* d_in, const int* in_sizes, int n_in,
                              void* d_out, int out_size)
{
    (void)in_sizes; (void)n_in; (void)out_size;
    const float* x  = (const float*)d_in[0];
    const float* Wq = (const float*)d_in[1];
    const float* Wk = (const float*)d_in[2];
    const float* Wv = (const float*)d_in[3];
    float* out = (float*)d_out;

    cudaFuncSetAttribute(qkv_tc,    cudaFuncAttributeMaxDynamicSharedMemorySize, SMEM_BYTES);
    cudaFuncSetAttribute(scores_tc, cudaFuncAttributeMaxDynamicSharedMemorySize, SMEM_BYTES);
    cudaFuncSetAttribute(pv_tc,     cudaFuncAttributeMaxDynamicSharedMemorySize, SMEM_BYTES);

    dim3 t32(32, 8);
    stage_x<<<dim3((BB * SS * DD) / (256 * 4)), 256>>>(x);
    transpose_w<<<dim3(DD / 32, DD / 32, 3), t32>>>(Wq, Wk, Wv);
    qkv_tc<<<dim3(DD / TILE, (BB * SS) / TILE, 3), 256, SMEM_BYTES>>>();
    transpose_v<<<dim3(DD / 32, SS / 32, BB), t32>>>();
    scores_tc<<<dim3(136, 1, BB), 256, SMEM_BYTES>>>();
    softmax_causal<<<dim3(BB * SS), 256>>>();
    pv_tc<<<dim3(DD / TILE, SS / TILE, BB), 256, SMEM_BYTES>>>(out);
}